// round 11
// baseline (speedup 1.0000x reference)
#include <cuda_runtime.h>
#include <cuda_bf16.h>
#include <math.h>
#include <stdint.h>

#define N_TOK   4096
#define D_MODEL 1024
#define D_FF    2048
#define N_EXP   8
#define ROWS    9216
#define TILE    128
#define LDA     40          /* padded SMEM row stride in bf16 (80B, conflict-free ldmatrix) */

#define BUF_BYTES   (128 * LDA * 2)          /* 10240 B per tile buffer */
#define AH_OFF      0
#define AL_OFF      (1 * BUF_BYTES)
#define BH_OFF      (2 * BUF_BYTES)
#define BL_OFF      (3 * BUF_BYTES)
#define STAGE_BYTES (4 * BUF_BYTES)          /* 40960 B */
#define NSTAGE      3
#define DSMEM_BYTES (NSTAGE * STAGE_BYTES)   /* 122880 B */

// ===================== helpers ==============================================
__device__ __forceinline__ uint32_t smem_u32(const void* p) {
    uint32_t a;
    asm("{ .reg .u64 t; cvta.to.shared.u64 t, %1; cvt.u32.u64 %0, t; }" : "=r"(a) : "l"(p));
    return a;
}
__device__ __forceinline__ void ldsm_x4(uint32_t& r0, uint32_t& r1, uint32_t& r2, uint32_t& r3,
                                        uint32_t addr) {
    asm volatile("ldmatrix.sync.aligned.m8n8.x4.shared.b16 {%0,%1,%2,%3}, [%4];"
                 : "=r"(r0), "=r"(r1), "=r"(r2), "=r"(r3) : "r"(addr));
}
__device__ __forceinline__ void mma16816(float* c, const uint32_t* a, uint32_t b0, uint32_t b1) {
    asm volatile(
        "mma.sync.aligned.m16n8k16.row.col.f32.bf16.bf16.f32 "
        "{%0,%1,%2,%3}, {%4,%5,%6,%7}, {%8,%9}, {%0,%1,%2,%3};"
        : "+f"(c[0]), "+f"(c[1]), "+f"(c[2]), "+f"(c[3])
        : "r"(a[0]), "r"(a[1]), "r"(a[2]), "r"(a[3]), "r"(b0), "r"(b1));
}
__device__ __forceinline__ void cp16(uint32_t saddr, const void* g, uint32_t src_sz) {
    asm volatile("cp.async.cg.shared.global [%0], [%1], 16, %2;"
                 :: "r"(saddr), "l"(g), "r"(src_sz));
}
#define CP_COMMIT() asm volatile("cp.async.commit_group;" ::: "memory")
#define CP_WAIT1()  asm volatile("cp.async.wait_group 1;" ::: "memory")

// ===================== scratch ==============================================
__device__ int   d_tok_exp[N_TOK * 2];
__device__ float d_tok_w[N_TOK * 2];
__device__ int   d_count[N_EXP];
__device__ int   d_off[N_EXP + 1];
__device__ int   d_cursor[N_EXP];
__device__ int   d_row_token[ROWS];
__device__ float d_row_weight[ROWS];

__device__ __nv_bfloat16 d_xh[(size_t)N_TOK * D_MODEL];
__device__ __nv_bfloat16 d_xl[(size_t)N_TOK * D_MODEL];
__device__ __nv_bfloat16 d_wguh[(size_t)N_EXP * 2 * D_FF * D_MODEL];
__device__ __nv_bfloat16 d_wgul[(size_t)N_EXP * 2 * D_FF * D_MODEL];
__device__ __nv_bfloat16 d_wdh[(size_t)N_EXP * D_MODEL * D_FF];
__device__ __nv_bfloat16 d_wdl[(size_t)N_EXP * D_MODEL * D_FF];
__device__ __nv_bfloat16 d_Hh[(size_t)ROWS * D_FF];
__device__ __nv_bfloat16 d_Hl[(size_t)ROWS * D_FF];

// ===================== small kernels ========================================
__global__ void init_kernel(float* __restrict__ out) {
    int i = blockIdx.x * blockDim.x + threadIdx.x;
    int stride = gridDim.x * blockDim.x;
    for (int j = i; j < N_TOK * D_MODEL; j += stride) out[j] = 0.f;
    if (i < ROWS) { d_row_token[i] = -1; d_row_weight[i] = 0.f; }
    if (i < N_EXP) d_count[i] = 0;
}

__global__ void split_kernel(const float* __restrict__ s,
                             __nv_bfloat16* __restrict__ hi,
                             __nv_bfloat16* __restrict__ lo, int n4) {
    int i = blockIdx.x * blockDim.x + threadIdx.x;
    if (i >= n4) return;
    float4 v = reinterpret_cast<const float4*>(s)[i];
    __nv_bfloat16 h0 = __float2bfloat16(v.x), h1 = __float2bfloat16(v.y);
    __nv_bfloat16 h2 = __float2bfloat16(v.z), h3 = __float2bfloat16(v.w);
    __nv_bfloat16 l0 = __float2bfloat16(v.x - __bfloat162float(h0));
    __nv_bfloat16 l1 = __float2bfloat16(v.y - __bfloat162float(h1));
    __nv_bfloat16 l2 = __float2bfloat16(v.z - __bfloat162float(h2));
    __nv_bfloat16 l3 = __float2bfloat16(v.w - __bfloat162float(h3));
    reinterpret_cast<__nv_bfloat162*>(hi)[2 * i]     = __halves2bfloat162(h0, h1);
    reinterpret_cast<__nv_bfloat162*>(hi)[2 * i + 1] = __halves2bfloat162(h2, h3);
    reinterpret_cast<__nv_bfloat162*>(lo)[2 * i]     = __halves2bfloat162(l0, l1);
    reinterpret_cast<__nv_bfloat162*>(lo)[2 * i + 1] = __halves2bfloat162(l2, l3);
}

__global__ void router_kernel(const float* __restrict__ x,
                              const float* __restrict__ wr) {
    int warp = (blockIdx.x * blockDim.x + threadIdx.x) >> 5;
    int lane = threadIdx.x & 31;
    if (warp >= N_TOK) return;
    const float* xr = x + (size_t)warp * D_MODEL;

    float logits[N_EXP];
#pragma unroll
    for (int e = 0; e < N_EXP; e++) {
        const float* w = wr + e * D_MODEL;
        float p = 0.f;
        for (int d = lane; d < D_MODEL; d += 32) p = fmaf(xr[d], w[d], p);
#pragma unroll
        for (int s = 16; s > 0; s >>= 1) p += __shfl_xor_sync(0xffffffffu, p, s);
        logits[e] = p;
    }
    if (lane == 0) {
        float mx = -3.4e38f;
#pragma unroll
        for (int e = 0; e < N_EXP; e++) {
            float v = fminf(fmaxf(logits[e], -1e4f), 1e4f);
            logits[e] = v; mx = fmaxf(mx, v);
        }
        float ex[N_EXP], s = 0.f;
#pragma unroll
        for (int e = 0; e < N_EXP; e++) { ex[e] = expf(logits[e] - mx); s += ex[e]; }
        float denom = s + 1e-8f;
        float probs[N_EXP];
#pragma unroll
        for (int e = 0; e < N_EXP; e++)
            probs[e] = fminf(fmaxf(ex[e] / denom, 1e-8f), 1.0f);
        int i0 = 0;
#pragma unroll
        for (int e = 1; e < N_EXP; e++) if (probs[e] > probs[i0]) i0 = e;
        int i1 = (i0 == 0) ? 1 : 0;
#pragma unroll
        for (int e = 0; e < N_EXP; e++)
            if (e != i0 && probs[e] > probs[i1]) i1 = e;
        float p0 = probs[i0], p1 = probs[i1];
        float rs = 1.f / (p0 + p1 + 1e-8f);
        d_tok_exp[2 * warp] = i0;  d_tok_exp[2 * warp + 1] = i1;
        d_tok_w[2 * warp] = p0 * rs; d_tok_w[2 * warp + 1] = p1 * rs;
        atomicAdd(&d_count[i0], 1); atomicAdd(&d_count[i1], 1);
    }
}

__global__ void offsets_kernel() {
    if (threadIdx.x == 0) {
        int o = 0;
        for (int e = 0; e < N_EXP; e++) {
            d_off[e] = o;
            o += ((d_count[e] + TILE - 1) / TILE) * TILE;
            d_cursor[e] = 0;
        }
        d_off[N_EXP] = o;
    }
}

__global__ void scatter_kernel() {
    int t = blockIdx.x * blockDim.x + threadIdx.x;
    if (t >= N_TOK) return;
#pragma unroll
    for (int k = 0; k < 2; k++) {
        int e = d_tok_exp[2 * t + k];
        int pos = d_off[e] + atomicAdd(&d_cursor[e], 1);
        d_row_token[pos]  = t;
        d_row_weight[pos] = d_tok_w[2 * t + k];
    }
}

// ===================== GEMM1: x(gather) @ wgu^T + fused SwiGLU -> Hh/Hl ======
// grid: (D_FF/64, ROWS/128). B tile: even row = gate(f), odd row = up(f),
// f = colStartF + (r>>1). Then each C-fragment column pair (c2, c2+1) is
// (gate(f), up(f)) for the same f — SwiGLU applies thread-locally.
// K = 1024. cp.async 3-stage pipeline.
__global__ __launch_bounds__(256, 1)
void gemm1_mma(void) {
    extern __shared__ __align__(16) char dyn[];
    __shared__ int stok[128];

    const int tid  = threadIdx.x;
    const int wid  = tid >> 5;
    const int lane = tid & 31;
    const int rowStart  = blockIdx.y * 128;
    const int colStartF = blockIdx.x * 64;   // f base in [0, D_FF)

    if (rowStart >= d_off[N_EXP]) return;
    int e = 0;
#pragma unroll
    for (int i = N_EXP - 1; i >= 0; i--) if (rowStart >= d_off[i]) { e = i; break; }

    if (tid < 128) stok[tid] = d_row_token[rowStart + tid];
    __syncthreads();

    const size_t wb = (size_t)e * 2 * D_FF * D_MODEL;
    const int wm = (wid & 1) * 64;
    const int wn = (wid >> 1) * 32;
    const uint32_t base = smem_u32(dyn);

    // per-thread load coords
    const int r0_ = tid >> 2, r1_ = r0_ + 64;
    const int u_  = tid & 3;
    // gate/up interleaved B row mapping
    const int rr0 = colStartF + (r0_ >> 1) + (r0_ & 1) * D_FF;
    const int rr1 = colStartF + (r1_ >> 1) + (r1_ & 1) * D_FF;

    float acc[4][4][4];
#pragma unroll
    for (int a = 0; a < 4; a++)
#pragma unroll
        for (int b = 0; b < 4; b++)
#pragma unroll
            for (int c = 0; c < 4; c++) acc[a][b][c] = 0.f;

#define G1_LOAD(stage, kt) do {                                                   \
    const uint32_t sb = base + (stage) * STAGE_BYTES;                             \
    const int k0 = (kt) * 32;                                                     \
    _Pragma("unroll")                                                             \
    for (int i = 0; i < 2; i++) {                                                 \
        int r  = i ? r1_ : r0_;                                                   \
        int rr = i ? rr1 : rr0;                                                   \
        uint32_t so = (uint32_t)((r * LDA + u_ * 8) * 2);                         \
        int t = stok[r];                                                          \
        uint32_t sz = (t >= 0) ? 16u : 0u;                                        \
        size_t ga = (size_t)(t >= 0 ? t : 0) * D_MODEL + k0 + u_ * 8;             \
        cp16(sb + AH_OFF + so, d_xh + ga, sz);                                    \
        cp16(sb + AL_OFF + so, d_xl + ga, sz);                                    \
        size_t gb = wb + (size_t)rr * D_MODEL + k0 + u_ * 8;                      \
        cp16(sb + BH_OFF + so, d_wguh + gb, 16u);                                 \
        cp16(sb + BL_OFF + so, d_wgul + gb, 16u);                                 \
    }                                                                             \
} while (0)

    G1_LOAD(0, 0);
    CP_COMMIT();
    G1_LOAD(1, 1);
    CP_COMMIT();

    const int NKT = D_MODEL / 32;
#pragma unroll 1
    for (int kt = 0; kt < NKT; kt++) {
        CP_WAIT1();
        __syncthreads();
        if (kt + 2 < NKT) G1_LOAD((kt + 2) % NSTAGE, kt + 2);
        CP_COMMIT();

        const uint32_t sb  = base + (kt % NSTAGE) * STAGE_BYTES;
        const uint32_t aAh = sb + AH_OFF, aAl = sb + AL_OFF;
        const uint32_t aBh = sb + BH_OFF, aBl = sb + BL_OFF;
#pragma unroll
        for (int ks = 0; ks < 2; ks++) {
            const int kk = ks * 16;
            uint32_t fAh[4][4], fAl[4][4], fBh[2][4], fBl[2][4];
#pragma unroll
            for (int mt = 0; mt < 4; mt++) {
                uint32_t off = (uint32_t)(((wm + mt * 16 + (lane & 15)) * LDA
                                           + kk + (lane >> 4) * 8) * 2);
                ldsm_x4(fAh[mt][0], fAh[mt][1], fAh[mt][2], fAh[mt][3], aAh + off);
                ldsm_x4(fAl[mt][0], fAl[mt][1], fAl[mt][2], fAl[mt][3], aAl + off);
            }
#pragma unroll
            for (int p = 0; p < 2; p++) {
                int n0 = wn + p * 16;
                uint32_t off = (uint32_t)(((n0 + (lane & 7) + (lane >> 4) * 8) * LDA
                                           + kk + ((lane >> 3) & 1) * 8) * 2);
                ldsm_x4(fBh[p][0], fBh[p][1], fBh[p][2], fBh[p][3], aBh + off);
                ldsm_x4(fBl[p][0], fBl[p][1], fBl[p][2], fBl[p][3], aBl + off);
            }
#pragma unroll
            for (int mt = 0; mt < 4; mt++)
#pragma unroll
                for (int nb = 0; nb < 4; nb++) {
                    int p = nb >> 1, h = (nb & 1) * 2;
                    mma16816(acc[mt][nb], fAh[mt], fBh[p][h], fBh[p][h + 1]);
                    mma16816(acc[mt][nb], fAh[mt], fBl[p][h], fBl[p][h + 1]);
                    mma16816(acc[mt][nb], fAl[mt], fBh[p][h], fBh[p][h + 1]);
                }
        }
    }
#undef G1_LOAD

    // fused SwiGLU epilogue: (c2, c2+1) = (gate, up) of f = colStartF + col/2
    const int g  = lane >> 2;
    const int c2 = (lane & 3) * 2;
#pragma unroll
    for (int mt = 0; mt < 4; mt++) {
        int row0 = rowStart + wm + mt * 16 + g;
#pragma unroll
        for (int nb = 0; nb < 4; nb++) {
            int fcol = colStartF + ((wn + nb * 8 + c2) >> 1);
            float g0 = acc[mt][nb][0], u0 = acc[mt][nb][1];
            float g1 = acc[mt][nb][2], u1 = acc[mt][nb][3];
            float h0 = g0 * u0 / (1.f + expf(-u0));
            float h1 = g1 * u1 / (1.f + expf(-u1));
            __nv_bfloat16 a0 = __float2bfloat16(h0);
            __nv_bfloat16 a1 = __float2bfloat16(h1);
            __nv_bfloat16 b0 = __float2bfloat16(h0 - __bfloat162float(a0));
            __nv_bfloat16 b1 = __float2bfloat16(h1 - __bfloat162float(a1));
            d_Hh[(size_t)row0 * D_FF + fcol]       = a0;
            d_Hl[(size_t)row0 * D_FF + fcol]       = b0;
            d_Hh[(size_t)(row0 + 8) * D_FF + fcol] = a1;
            d_Hl[(size_t)(row0 + 8) * D_FF + fcol] = b1;
        }
    }
}

// ===================== GEMM2: H @ wd^T -> weighted scatter ===================
// grid: (1024/128, ROWS/128). K = 2048. cp.async 3-stage pipeline.
__global__ __launch_bounds__(256, 1)
void gemm2_mma(float* __restrict__ out) {
    extern __shared__ __align__(16) char dyn[];
    __shared__ int   stok[128];
    __shared__ float swt[128];

    const int tid  = threadIdx.x;
    const int wid  = tid >> 5;
    const int lane = tid & 31;
    const int rowStart = blockIdx.y * 128;
    const int colStart = blockIdx.x * 128;   // d col (0..1023)

    if (rowStart >= d_off[N_EXP]) return;
    int e = 0;
#pragma unroll
    for (int i = N_EXP - 1; i >= 0; i--) if (rowStart >= d_off[i]) { e = i; break; }

    if (tid < 128) {
        stok[tid] = d_row_token[rowStart + tid];
        swt[tid]  = d_row_weight[rowStart + tid];
    }
    __syncthreads();

    const size_t wb = (size_t)e * D_MODEL * D_FF;
    const int wm = (wid & 1) * 64;
    const int wn = (wid >> 1) * 32;
    const uint32_t base = smem_u32(dyn);

    const int r0_ = tid >> 2, r1_ = r0_ + 64;
    const int u_  = tid & 3;

    float acc[4][4][4];
#pragma unroll
    for (int a = 0; a < 4; a++)
#pragma unroll
        for (int b = 0; b < 4; b++)
#pragma unroll
            for (int c = 0; c < 4; c++) acc[a][b][c] = 0.f;

#define G2_LOAD(stage, kt) do {                                                   \
    const uint32_t sb = base + (stage) * STAGE_BYTES;                             \
    const int k0 = (kt) * 32;                                                     \
    _Pragma("unroll")                                                             \
    for (int i = 0; i < 2; i++) {                                                 \
        int r = i ? r1_ : r0_;                                                    \
        uint32_t so = (uint32_t)((r * LDA + u_ * 8) * 2);                         \
        size_t ga = (size_t)(rowStart + r) * D_FF + k0 + u_ * 8;                  \
        cp16(sb + AH_OFF + so, d_Hh + ga, 16u);                                   \
        cp16(sb + AL_OFF + so, d_Hl + ga, 16u);                                   \
        size_t gb = wb + (size_t)(colStart + r) * D_FF + k0 + u_ * 8;             \
        cp16(sb + BH_OFF + so, d_wdh + gb, 16u);                                  \
        cp16(sb + BL_OFF + so, d_wdl + gb, 16u);                                  \
    }                                                                             \
} while (0)

    G2_LOAD(0, 0);
    CP_COMMIT();
    G2_LOAD(1, 1);
    CP_COMMIT();

    const int NKT = D_FF / 32;
#pragma unroll 1
    for (int kt = 0; kt < NKT; kt++) {
        CP_WAIT1();
        __syncthreads();
        if (kt + 2 < NKT) G2_LOAD((kt + 2) % NSTAGE, kt + 2);
        CP_COMMIT();

        const uint32_t sb  = base + (kt % NSTAGE) * STAGE_BYTES;
        const uint32_t aAh = sb + AH_OFF, aAl = sb + AL_OFF;
        const uint32_t aBh = sb + BH_OFF, aBl = sb + BL_OFF;
#pragma unroll
        for (int ks = 0; ks < 2; ks++) {
            const int kk = ks * 16;
            uint32_t fAh[4][4], fAl[4][4], fBh[2][4], fBl[2][4];
#pragma unroll
            for (int mt = 0; mt < 4; mt++) {
                uint32_t off = (uint32_t)(((wm + mt * 16 + (lane & 15)) * LDA
                                           + kk + (lane >> 4) * 8) * 2);
                ldsm_x4(fAh[mt][0], fAh[mt][1], fAh[mt][2], fAh[mt][3], aAh + off);
                ldsm_x4(fAl[mt][0], fAl[mt][1], fAl[mt][2], fAl[mt][3], aAl + off);
            }
#pragma unroll
            for (int p = 0; p < 2; p++) {
                int n0 = wn + p * 16;
                uint32_t off = (uint32_t)(((n0 + (lane & 7) + (lane >> 4) * 8) * LDA
                                           + kk + ((lane >> 3) & 1) * 8) * 2);
                ldsm_x4(fBh[p][0], fBh[p][1], fBh[p][2], fBh[p][3], aBh + off);
                ldsm_x4(fBl[p][0], fBl[p][1], fBl[p][2], fBl[p][3], aBl + off);
            }
#pragma unroll
            for (int mt = 0; mt < 4; mt++)
#pragma unroll
                for (int nb = 0; nb < 4; nb++) {
                    int p = nb >> 1, h = (nb & 1) * 2;
                    mma16816(acc[mt][nb], fAh[mt], fBh[p][h], fBh[p][h + 1]);
                    mma16816(acc[mt][nb], fAh[mt], fBl[p][h], fBl[p][h + 1]);
                    mma16816(acc[mt][nb], fAl[mt], fBh[p][h], fBh[p][h + 1]);
                }
        }
    }
#undef G2_LOAD

    // epilogue: weighted scatter-add (each out element gets exactly 2 fp32 adds)
    const int g  = lane >> 2;
    const int c2 = (lane & 3) * 2;
#pragma unroll
    for (int mt = 0; mt < 4; mt++) {
        int r0 = wm + mt * 16 + g;
        int t0 = stok[r0],     t1 = stok[r0 + 8];
        float w0 = swt[r0],    w1 = swt[r0 + 8];
#pragma unroll
        for (int nb = 0; nb < 4; nb++) {
            int col = colStart + wn + nb * 8 + c2;
            if (t0 >= 0) {
                float* o = out + (size_t)t0 * D_MODEL + col;
                atomicAdd(o,     w0 * acc[mt][nb][0]);
                atomicAdd(o + 1, w0 * acc[mt][nb][1]);
            }
            if (t1 >= 0) {
                float* o = out + (size_t)t1 * D_MODEL + col;
                atomicAdd(o,     w1 * acc[mt][nb][2]);
                atomicAdd(o + 1, w1 * acc[mt][nb][3]);
            }
        }
    }
}

// ===================== launch ================================================
extern "C" void kernel_launch(void* const* d_in, const int* in_sizes, int n_in,
                              void* d_out, int out_size) {
    const float* x   = (const float*)d_in[0];
    const float* wr  = (const float*)d_in[1];
    const float* wgu = (const float*)d_in[2];
    const float* wd  = (const float*)d_in[3];
    float* out = (float*)d_out;

    cudaFuncSetAttribute(gemm1_mma, cudaFuncAttributeMaxDynamicSharedMemorySize, DSMEM_BYTES);
    cudaFuncSetAttribute(gemm2_mma, cudaFuncAttributeMaxDynamicSharedMemorySize, DSMEM_BYTES);

    init_kernel<<<2048, 512>>>(out);

    __nv_bfloat16 *xh, *xl, *wguh, *wgul, *wdh, *wdl;
    cudaGetSymbolAddress((void**)&xh,   d_xh);
    cudaGetSymbolAddress((void**)&xl,   d_xl);
    cudaGetSymbolAddress((void**)&wguh, d_wguh);
    cudaGetSymbolAddress((void**)&wgul, d_wgul);
    cudaGetSymbolAddress((void**)&wdh,  d_wdh);
    cudaGetSymbolAddress((void**)&wdl,  d_wdl);

    { int n4 = N_TOK * D_MODEL / 4;
      split_kernel<<<(n4 + 255) / 256, 256>>>(x, xh, xl, n4); }
    { int n4 = N_EXP * 2 * D_FF * D_MODEL / 4;
      split_kernel<<<(n4 + 255) / 256, 256>>>(wgu, wguh, wgul, n4); }
    { int n4 = N_EXP * D_MODEL * D_FF / 4;
      split_kernel<<<(n4 + 255) / 256, 256>>>(wd, wdh, wdl, n4); }

    router_kernel<<<N_TOK / 8, 256>>>(x, wr);
    offsets_kernel<<<1, 32>>>();
    scatter_kernel<<<(N_TOK + 255) / 256, 256>>>();

    gemm1_mma<<<dim3(D_FF / 64, ROWS / 128), 256, DSMEM_BYTES>>>();
    gemm2_mma<<<dim3(D_MODEL / 128, ROWS / 128), 256, DSMEM_BYTES>>>(out);
}

// round 13
// speedup vs baseline: 1.2899x; 1.2899x over previous
#include <cuda_runtime.h>
#include <cuda_fp16.h>
#include <math.h>
#include <stdint.h>

#define N_TOK   4096
#define D_MODEL 1024
#define D_FF    2048
#define N_EXP   8
#define ROWS    9216
#define TILE    128
#define LDA     40          /* padded SMEM row stride in halves (80B, conflict-free ldmatrix) */

#define BUF_BYTES   (128 * LDA * 2)          /* 10240 B per tile buffer */
#define A_OFF       0
#define BH_OFF      (1 * BUF_BYTES)
#define BL_OFF      (2 * BUF_BYTES)
#define STAGE_BYTES (3 * BUF_BYTES)          /* 30720 B */
#define NSTAGE      3
#define DSMEM_BYTES (NSTAGE * STAGE_BYTES)   /* 92160 B */

#define LO_SCALE    4096.0f                  /* 2^12 : keeps weight residuals normal fp16 */
#define LO_INV      (1.0f / 4096.0f)

// ===================== helpers ==============================================
__device__ __forceinline__ uint32_t smem_u32(const void* p) {
    uint32_t a;
    asm("{ .reg .u64 t; cvta.to.shared.u64 t, %1; cvt.u32.u64 %0, t; }" : "=r"(a) : "l"(p));
    return a;
}
__device__ __forceinline__ void ldsm_x4(uint32_t& r0, uint32_t& r1, uint32_t& r2, uint32_t& r3,
                                        uint32_t addr) {
    asm volatile("ldmatrix.sync.aligned.m8n8.x4.shared.b16 {%0,%1,%2,%3}, [%4];"
                 : "=r"(r0), "=r"(r1), "=r"(r2), "=r"(r3) : "r"(addr));
}
__device__ __forceinline__ void mma16816(float* c, const uint32_t* a, uint32_t b0, uint32_t b1) {
    asm volatile(
        "mma.sync.aligned.m16n8k16.row.col.f32.f16.f16.f32 "
        "{%0,%1,%2,%3}, {%4,%5,%6,%7}, {%8,%9}, {%0,%1,%2,%3};"
        : "+f"(c[0]), "+f"(c[1]), "+f"(c[2]), "+f"(c[3])
        : "r"(a[0]), "r"(a[1]), "r"(a[2]), "r"(a[3]), "r"(b0), "r"(b1));
}
__device__ __forceinline__ void cp16(uint32_t saddr, const void* g, uint32_t src_sz) {
    asm volatile("cp.async.cg.shared.global [%0], [%1], 16, %2;"
                 :: "r"(saddr), "l"(g), "r"(src_sz));
}
#define CP_COMMIT() asm volatile("cp.async.commit_group;" ::: "memory")
#define CP_WAIT1()  asm volatile("cp.async.wait_group 1;" ::: "memory")

// ===================== scratch ==============================================
__device__ int   d_tok_exp[N_TOK * 2];
__device__ float d_tok_w[N_TOK * 2];
__device__ int   d_count[N_EXP];
__device__ int   d_off[N_EXP + 1];
__device__ int   d_cursor[N_EXP];
__device__ int   d_row_token[ROWS];
__device__ float d_row_weight[ROWS];

__device__ __half d_x16[(size_t)N_TOK * D_MODEL];
__device__ __half d_wguh[(size_t)N_EXP * 2 * D_FF * D_MODEL];
__device__ __half d_wgul[(size_t)N_EXP * 2 * D_FF * D_MODEL];   // residual * 2^12
__device__ __half d_wdh[(size_t)N_EXP * D_MODEL * D_FF];
__device__ __half d_wdl[(size_t)N_EXP * D_MODEL * D_FF];        // residual * 2^12
__device__ __half d_H[(size_t)ROWS * D_FF];

// ===================== small kernels ========================================
__global__ void init_kernel(float* __restrict__ out) {
    int i = blockIdx.x * blockDim.x + threadIdx.x;
    int stride = gridDim.x * blockDim.x;
    for (int j = i; j < N_TOK * D_MODEL; j += stride) out[j] = 0.f;
    if (i < ROWS) { d_row_token[i] = -1; d_row_weight[i] = 0.f; }
    if (i < N_EXP) d_count[i] = 0;
}

// fp32 -> fp16 (x only)
__global__ void splitx_kernel(const float* __restrict__ s, __half* __restrict__ hi, int n4) {
    int i = blockIdx.x * blockDim.x + threadIdx.x;
    if (i >= n4) return;
    float4 v = reinterpret_cast<const float4*>(s)[i];
    reinterpret_cast<__half2*>(hi)[2 * i]     = __floats2half2_rn(v.x, v.y);
    reinterpret_cast<__half2*>(hi)[2 * i + 1] = __floats2half2_rn(v.z, v.w);
}

// fp32 -> fp16 hi + fp16 (residual * 2^12)
__global__ void splitw_kernel(const float* __restrict__ s,
                              __half* __restrict__ hi,
                              __half* __restrict__ lo, int n4) {
    int i = blockIdx.x * blockDim.x + threadIdx.x;
    if (i >= n4) return;
    float4 v = reinterpret_cast<const float4*>(s)[i];
    __half h0 = __float2half_rn(v.x), h1 = __float2half_rn(v.y);
    __half h2 = __float2half_rn(v.z), h3 = __float2half_rn(v.w);
    float l0 = (v.x - __half2float(h0)) * LO_SCALE;
    float l1 = (v.y - __half2float(h1)) * LO_SCALE;
    float l2 = (v.z - __half2float(h2)) * LO_SCALE;
    float l3 = (v.w - __half2float(h3)) * LO_SCALE;
    reinterpret_cast<__half2*>(hi)[2 * i]     = __halves2half2(h0, h1);
    reinterpret_cast<__half2*>(hi)[2 * i + 1] = __halves2half2(h2, h3);
    reinterpret_cast<__half2*>(lo)[2 * i]     = __floats2half2_rn(l0, l1);
    reinterpret_cast<__half2*>(lo)[2 * i + 1] = __floats2half2_rn(l2, l3);
}

__global__ void router_kernel(const float* __restrict__ x,
                              const float* __restrict__ wr) {
    int warp = (blockIdx.x * blockDim.x + threadIdx.x) >> 5;
    int lane = threadIdx.x & 31;
    if (warp >= N_TOK) return;
    const float* xr = x + (size_t)warp * D_MODEL;

    float logits[N_EXP];
#pragma unroll
    for (int e = 0; e < N_EXP; e++) {
        const float* w = wr + e * D_MODEL;
        float p = 0.f;
        for (int d = lane; d < D_MODEL; d += 32) p = fmaf(xr[d], w[d], p);
#pragma unroll
        for (int s = 16; s > 0; s >>= 1) p += __shfl_xor_sync(0xffffffffu, p, s);
        logits[e] = p;
    }
    if (lane == 0) {
        float mx = -3.4e38f;
#pragma unroll
        for (int e = 0; e < N_EXP; e++) {
            float v = fminf(fmaxf(logits[e], -1e4f), 1e4f);
            logits[e] = v; mx = fmaxf(mx, v);
        }
        float ex[N_EXP], s = 0.f;
#pragma unroll
        for (int e = 0; e < N_EXP; e++) { ex[e] = expf(logits[e] - mx); s += ex[e]; }
        float denom = s + 1e-8f;
        float probs[N_EXP];
#pragma unroll
        for (int e = 0; e < N_EXP; e++)
            probs[e] = fminf(fmaxf(ex[e] / denom, 1e-8f), 1.0f);
        int i0 = 0;
#pragma unroll
        for (int e = 1; e < N_EXP; e++) if (probs[e] > probs[i0]) i0 = e;
        int i1 = (i0 == 0) ? 1 : 0;
#pragma unroll
        for (int e = 0; e < N_EXP; e++)
            if (e != i0 && probs[e] > probs[i1]) i1 = e;
        float p0 = probs[i0], p1 = probs[i1];
        float rs = 1.f / (p0 + p1 + 1e-8f);
        d_tok_exp[2 * warp] = i0;  d_tok_exp[2 * warp + 1] = i1;
        d_tok_w[2 * warp] = p0 * rs; d_tok_w[2 * warp + 1] = p1 * rs;
        atomicAdd(&d_count[i0], 1); atomicAdd(&d_count[i1], 1);
    }
}

__global__ void offsets_kernel() {
    if (threadIdx.x == 0) {
        int o = 0;
        for (int e = 0; e < N_EXP; e++) {
            d_off[e] = o;
            o += ((d_count[e] + TILE - 1) / TILE) * TILE;
            d_cursor[e] = 0;
        }
        d_off[N_EXP] = o;
    }
}

__global__ void scatter_kernel() {
    int t = blockIdx.x * blockDim.x + threadIdx.x;
    if (t >= N_TOK) return;
#pragma unroll
    for (int k = 0; k < 2; k++) {
        int e = d_tok_exp[2 * t + k];
        int pos = d_off[e] + atomicAdd(&d_cursor[e], 1);
        d_row_token[pos]  = t;
        d_row_weight[pos] = d_tok_w[2 * t + k];
    }
}

// ===================== GEMM1: x(gather) @ wgu^T + fused SwiGLU -> d_H ========
// grid: (D_FF/64, ROWS/128). B rows interleaved: even = gate(f), odd = up(f).
// 2-term fp16: acc = A*Bh ; accC = A*(Bl*2^12); result = acc + accC*2^-12.
__global__ __launch_bounds__(256, 1)
void gemm1_mma(void) {
    extern __shared__ __align__(16) char dyn[];
    __shared__ int stok[128];

    const int tid  = threadIdx.x;
    const int wid  = tid >> 5;
    const int lane = tid & 31;
    const int rowStart  = blockIdx.y * 128;
    const int colStartF = blockIdx.x * 64;

    if (rowStart >= d_off[N_EXP]) return;
    int e = 0;
#pragma unroll
    for (int i = N_EXP - 1; i >= 0; i--) if (rowStart >= d_off[i]) { e = i; break; }

    if (tid < 128) stok[tid] = d_row_token[rowStart + tid];
    __syncthreads();

    const size_t wb = (size_t)e * 2 * D_FF * D_MODEL;
    const int wm = (wid & 1) * 64;
    const int wn = (wid >> 1) * 32;
    const uint32_t base = smem_u32(dyn);

    const int r0_ = tid >> 2, r1_ = r0_ + 64;
    const int u_  = tid & 3;
    const int rr0 = colStartF + (r0_ >> 1) + (r0_ & 1) * D_FF;
    const int rr1 = colStartF + (r1_ >> 1) + (r1_ & 1) * D_FF;

    float acc[4][4][4], accC[4][4][4];
#pragma unroll
    for (int a = 0; a < 4; a++)
#pragma unroll
        for (int b = 0; b < 4; b++)
#pragma unroll
            for (int c = 0; c < 4; c++) { acc[a][b][c] = 0.f; accC[a][b][c] = 0.f; }

#define G1_LOAD(stage, kt) do {                                                   \
    const uint32_t sb = base + (stage) * STAGE_BYTES;                             \
    const int k0 = (kt) * 32;                                                     \
    _Pragma("unroll")                                                             \
    for (int i = 0; i < 2; i++) {                                                 \
        int r  = i ? r1_ : r0_;                                                   \
        int rr = i ? rr1 : rr0;                                                   \
        uint32_t so = (uint32_t)((r * LDA + u_ * 8) * 2);                         \
        int t = stok[r];                                                          \
        uint32_t sz = (t >= 0) ? 16u : 0u;                                        \
        size_t ga = (size_t)(t >= 0 ? t : 0) * D_MODEL + k0 + u_ * 8;             \
        cp16(sb + A_OFF + so, d_x16 + ga, sz);                                    \
        size_t gb = wb + (size_t)rr * D_MODEL + k0 + u_ * 8;                      \
        cp16(sb + BH_OFF + so, d_wguh + gb, 16u);                                 \
        cp16(sb + BL_OFF + so, d_wgul + gb, 16u);                                 \
    }                                                                             \
} while (0)

    G1_LOAD(0, 0);
    CP_COMMIT();
    G1_LOAD(1, 1);
    CP_COMMIT();

    const int NKT = D_MODEL / 32;
#pragma unroll 1
    for (int kt = 0; kt < NKT; kt++) {
        CP_WAIT1();
        __syncthreads();
        if (kt + 2 < NKT) G1_LOAD((kt + 2) % NSTAGE, kt + 2);
        CP_COMMIT();

        const uint32_t sb  = base + (kt % NSTAGE) * STAGE_BYTES;
        const uint32_t aA  = sb + A_OFF;
        const uint32_t aBh = sb + BH_OFF, aBl = sb + BL_OFF;
#pragma unroll
        for (int ks = 0; ks < 2; ks++) {
            const int kk = ks * 16;
            uint32_t fA[4][4], fBh[2][4], fBl[2][4];
#pragma unroll
            for (int mt = 0; mt < 4; mt++) {
                uint32_t off = (uint32_t)(((wm + mt * 16 + (lane & 15)) * LDA
                                           + kk + (lane >> 4) * 8) * 2);
                ldsm_x4(fA[mt][0], fA[mt][1], fA[mt][2], fA[mt][3], aA + off);
            }
#pragma unroll
            for (int p = 0; p < 2; p++) {
                int n0 = wn + p * 16;
                uint32_t off = (uint32_t)(((n0 + (lane & 7) + (lane >> 4) * 8) * LDA
                                           + kk + ((lane >> 3) & 1) * 8) * 2);
                ldsm_x4(fBh[p][0], fBh[p][1], fBh[p][2], fBh[p][3], aBh + off);
                ldsm_x4(fBl[p][0], fBl[p][1], fBl[p][2], fBl[p][3], aBl + off);
            }
#pragma unroll
            for (int mt = 0; mt < 4; mt++)
#pragma unroll
                for (int nb = 0; nb < 4; nb++) {
                    int p = nb >> 1, h = (nb & 1) * 2;
                    mma16816(acc[mt][nb],  fA[mt], fBh[p][h], fBh[p][h + 1]);
                    mma16816(accC[mt][nb], fA[mt], fBl[p][h], fBl[p][h + 1]);
                }
        }
    }
#undef G1_LOAD

    // fused SwiGLU epilogue: column pair = (gate, up) of f = colStartF + col/2
    const int g  = lane >> 2;
    const int c2 = (lane & 3) * 2;
#pragma unroll
    for (int mt = 0; mt < 4; mt++) {
        int row0 = rowStart + wm + mt * 16 + g;
#pragma unroll
        for (int nb = 0; nb < 4; nb++) {
            int fcol = colStartF + ((wn + nb * 8 + c2) >> 1);
            float g0 = acc[mt][nb][0] + accC[mt][nb][0] * LO_INV;
            float u0 = acc[mt][nb][1] + accC[mt][nb][1] * LO_INV;
            float g1 = acc[mt][nb][2] + accC[mt][nb][2] * LO_INV;
            float u1 = acc[mt][nb][3] + accC[mt][nb][3] * LO_INV;
            float h0 = g0 * u0 / (1.f + expf(-u0));
            float h1 = g1 * u1 / (1.f + expf(-u1));
            d_H[(size_t)row0 * D_FF + fcol]       = __float2half_rn(h0);
            d_H[(size_t)(row0 + 8) * D_FF + fcol] = __float2half_rn(h1);
        }
    }
}

// ===================== GEMM2: H @ wd^T -> weighted scatter ===================
// grid: (1024/128, ROWS/128). K = 2048. 2-term fp16.
__global__ __launch_bounds__(256, 1)
void gemm2_mma(float* __restrict__ out) {
    extern __shared__ __align__(16) char dyn[];
    __shared__ int   stok[128];
    __shared__ float swt[128];

    const int tid  = threadIdx.x;
    const int wid  = tid >> 5;
    const int lane = tid & 31;
    const int rowStart = blockIdx.y * 128;
    const int colStart = blockIdx.x * 128;

    if (rowStart >= d_off[N_EXP]) return;
    int e = 0;
#pragma unroll
    for (int i = N_EXP - 1; i >= 0; i--) if (rowStart >= d_off[i]) { e = i; break; }

    if (tid < 128) {
        stok[tid] = d_row_token[rowStart + tid];
        swt[tid]  = d_row_weight[rowStart + tid];
    }
    __syncthreads();

    const size_t wb = (size_t)e * D_MODEL * D_FF;
    const int wm = (wid & 1) * 64;
    const int wn = (wid >> 1) * 32;
    const uint32_t base = smem_u32(dyn);

    const int r0_ = tid >> 2, r1_ = r0_ + 64;
    const int u_  = tid & 3;

    float acc[4][4][4], accC[4][4][4];
#pragma unroll
    for (int a = 0; a < 4; a++)
#pragma unroll
        for (int b = 0; b < 4; b++)
#pragma unroll
            for (int c = 0; c < 4; c++) { acc[a][b][c] = 0.f; accC[a][b][c] = 0.f; }

#define G2_LOAD(stage, kt) do {                                                   \
    const uint32_t sb = base + (stage) * STAGE_BYTES;                             \
    const int k0 = (kt) * 32;                                                     \
    _Pragma("unroll")                                                             \
    for (int i = 0; i < 2; i++) {                                                 \
        int r = i ? r1_ : r0_;                                                    \
        uint32_t so = (uint32_t)((r * LDA + u_ * 8) * 2);                         \
        size_t ga = (size_t)(rowStart + r) * D_FF + k0 + u_ * 8;                  \
        cp16(sb + A_OFF + so, d_H + ga, 16u);                                     \
        size_t gb = wb + (size_t)(colStart + r) * D_FF + k0 + u_ * 8;             \
        cp16(sb + BH_OFF + so, d_wdh + gb, 16u);                                  \
        cp16(sb + BL_OFF + so, d_wdl + gb, 16u);                                  \
    }                                                                             \
} while (0)

    G2_LOAD(0, 0);
    CP_COMMIT();
    G2_LOAD(1, 1);
    CP_COMMIT();

    const int NKT = D_FF / 32;
#pragma unroll 1
    for (int kt = 0; kt < NKT; kt++) {
        CP_WAIT1();
        __syncthreads();
        if (kt + 2 < NKT) G2_LOAD((kt + 2) % NSTAGE, kt + 2);
        CP_COMMIT();

        const uint32_t sb  = base + (kt % NSTAGE) * STAGE_BYTES;
        const uint32_t aA  = sb + A_OFF;
        const uint32_t aBh = sb + BH_OFF, aBl = sb + BL_OFF;
#pragma unroll
        for (int ks = 0; ks < 2; ks++) {
            const int kk = ks * 16;
            uint32_t fA[4][4], fBh[2][4], fBl[2][4];
#pragma unroll
            for (int mt = 0; mt < 4; mt++) {
                uint32_t off = (uint32_t)(((wm + mt * 16 + (lane & 15)) * LDA
                                           + kk + (lane >> 4) * 8) * 2);
                ldsm_x4(fA[mt][0], fA[mt][1], fA[mt][2], fA[mt][3], aA + off);
            }
#pragma unroll
            for (int p = 0; p < 2; p++) {
                int n0 = wn + p * 16;
                uint32_t off = (uint32_t)(((n0 + (lane & 7) + (lane >> 4) * 8) * LDA
                                           + kk + ((lane >> 3) & 1) * 8) * 2);
                ldsm_x4(fBh[p][0], fBh[p][1], fBh[p][2], fBh[p][3], aBh + off);
                ldsm_x4(fBl[p][0], fBl[p][1], fBl[p][2], fBl[p][3], aBl + off);
            }
#pragma unroll
            for (int mt = 0; mt < 4; mt++)
#pragma unroll
                for (int nb = 0; nb < 4; nb++) {
                    int p = nb >> 1, h = (nb & 1) * 2;
                    mma16816(acc[mt][nb],  fA[mt], fBh[p][h], fBh[p][h + 1]);
                    mma16816(accC[mt][nb], fA[mt], fBl[p][h], fBl[p][h + 1]);
                }
        }
    }
#undef G2_LOAD

    // epilogue: weighted scatter-add (each out element gets exactly 2 fp32 adds)
    const int g  = lane >> 2;
    const int c2 = (lane & 3) * 2;
#pragma unroll
    for (int mt = 0; mt < 4; mt++) {
        int r0 = wm + mt * 16 + g;
        int t0 = stok[r0],     t1 = stok[r0 + 8];
        float w0 = swt[r0],    w1 = swt[r0 + 8];
#pragma unroll
        for (int nb = 0; nb < 4; nb++) {
            int col = colStart + wn + nb * 8 + c2;
            if (t0 >= 0) {
                float* o = out + (size_t)t0 * D_MODEL + col;
                atomicAdd(o,     w0 * (acc[mt][nb][0] + accC[mt][nb][0] * LO_INV));
                atomicAdd(o + 1, w0 * (acc[mt][nb][1] + accC[mt][nb][1] * LO_INV));
            }
            if (t1 >= 0) {
                float* o = out + (size_t)t1 * D_MODEL + col;
                atomicAdd(o,     w1 * (acc[mt][nb][2] + accC[mt][nb][2] * LO_INV));
                atomicAdd(o + 1, w1 * (acc[mt][nb][3] + accC[mt][nb][3] * LO_INV));
            }
        }
    }
}

// ===================== launch ================================================
extern "C" void kernel_launch(void* const* d_in, const int* in_sizes, int n_in,
                              void* d_out, int out_size) {
    const float* x   = (const float*)d_in[0];
    const float* wr  = (const float*)d_in[1];
    const float* wgu = (const float*)d_in[2];
    const float* wd  = (const float*)d_in[3];
    float* out = (float*)d_out;

    cudaFuncSetAttribute(gemm1_mma, cudaFuncAttributeMaxDynamicSharedMemorySize, DSMEM_BYTES);
    cudaFuncSetAttribute(gemm2_mma, cudaFuncAttributeMaxDynamicSharedMemorySize, DSMEM_BYTES);

    init_kernel<<<2048, 512>>>(out);

    __half *x16, *wguh, *wgul, *wdh, *wdl;
    cudaGetSymbolAddress((void**)&x16,  d_x16);
    cudaGetSymbolAddress((void**)&wguh, d_wguh);
    cudaGetSymbolAddress((void**)&wgul, d_wgul);
    cudaGetSymbolAddress((void**)&wdh,  d_wdh);
    cudaGetSymbolAddress((void**)&wdl,  d_wdl);

    { int n4 = N_TOK * D_MODEL / 4;
      splitx_kernel<<<(n4 + 255) / 256, 256>>>(x, x16, n4); }
    { int n4 = N_EXP * 2 * D_FF * D_MODEL / 4;
      splitw_kernel<<<(n4 + 255) / 256, 256>>>(wgu, wguh, wgul, n4); }
    { int n4 = N_EXP * D_MODEL * D_FF / 4;
      splitw_kernel<<<(n4 + 255) / 256, 256>>>(wd, wdh, wdl, n4); }

    router_kernel<<<N_TOK / 8, 256>>>(x, wr);
    offsets_kernel<<<1, 32>>>();
    scatter_kernel<<<(N_TOK + 255) / 256, 256>>>();

    gemm1_mma<<<dim3(D_FF / 64, ROWS / 128), 256, DSMEM_BYTES>>>();
    gemm2_mma<<<dim3(D_MODEL / 128, ROWS / 128), 256, DSMEM_BYTES>>>(out);
}

// round 14
// speedup vs baseline: 1.3631x; 1.0567x over previous
#include <cuda_runtime.h>
#include <cuda_fp16.h>
#include <math.h>
#include <stdint.h>

#define N_TOK   4096
#define D_MODEL 1024
#define D_FF    2048
#define N_EXP   8
#define ROWS    9216
#define TILE    128
#define LDA     40          /* padded SMEM row stride in halves (80B, conflict-free ldmatrix) */

#define BUF_BYTES   (128 * LDA * 2)          /* 10240 B per tile buffer */
#define A_OFF       0
#define B_OFF       (1 * BUF_BYTES)
#define STAGE_BYTES (2 * BUF_BYTES)          /* 20480 B */
#define NSTAGE      3
#define DSMEM_BYTES (NSTAGE * STAGE_BYTES)   /* 61440 B */

// ===================== helpers ==============================================
__device__ __forceinline__ uint32_t smem_u32(const void* p) {
    uint32_t a;
    asm("{ .reg .u64 t; cvta.to.shared.u64 t, %1; cvt.u32.u64 %0, t; }" : "=r"(a) : "l"(p));
    return a;
}
__device__ __forceinline__ void ldsm_x4(uint32_t& r0, uint32_t& r1, uint32_t& r2, uint32_t& r3,
                                        uint32_t addr) {
    asm volatile("ldmatrix.sync.aligned.m8n8.x4.shared.b16 {%0,%1,%2,%3}, [%4];"
                 : "=r"(r0), "=r"(r1), "=r"(r2), "=r"(r3) : "r"(addr));
}
__device__ __forceinline__ void mma16816(float* c, const uint32_t* a, uint32_t b0, uint32_t b1) {
    asm volatile(
        "mma.sync.aligned.m16n8k16.row.col.f32.f16.f16.f32 "
        "{%0,%1,%2,%3}, {%4,%5,%6,%7}, {%8,%9}, {%0,%1,%2,%3};"
        : "+f"(c[0]), "+f"(c[1]), "+f"(c[2]), "+f"(c[3])
        : "r"(a[0]), "r"(a[1]), "r"(a[2]), "r"(a[3]), "r"(b0), "r"(b1));
}
__device__ __forceinline__ void cp16(uint32_t saddr, const void* g, uint32_t src_sz) {
    asm volatile("cp.async.cg.shared.global [%0], [%1], 16, %2;"
                 :: "r"(saddr), "l"(g), "r"(src_sz));
}
#define CP_COMMIT() asm volatile("cp.async.commit_group;" ::: "memory")
#define CP_WAIT1()  asm volatile("cp.async.wait_group 1;" ::: "memory")

// ===================== scratch ==============================================
__device__ int   d_tok_exp[N_TOK * 2];
__device__ float d_tok_w[N_TOK * 2];
__device__ int   d_count[N_EXP];
__device__ int   d_off[N_EXP + 1];
__device__ int   d_cursor[N_EXP];
__device__ int   d_row_token[ROWS];
__device__ float d_row_weight[ROWS];

__device__ __half d_x16[(size_t)N_TOK * D_MODEL];
__device__ __half d_wgu16[(size_t)N_EXP * 2 * D_FF * D_MODEL];
__device__ __half d_wd16[(size_t)N_EXP * D_MODEL * D_FF];
__device__ __half d_H[(size_t)ROWS * D_FF];

// ===================== small kernels ========================================
__global__ void init_kernel(float* __restrict__ out) {
    int i = blockIdx.x * blockDim.x + threadIdx.x;
    int stride = gridDim.x * blockDim.x;
    for (int j = i; j < N_TOK * D_MODEL; j += stride) out[j] = 0.f;
    if (i < ROWS) { d_row_token[i] = -1; d_row_weight[i] = 0.f; }
    if (i < N_EXP) d_count[i] = 0;
}

// fp32 -> fp16
__global__ void cvt16_kernel(const float* __restrict__ s, __half* __restrict__ o, int n4) {
    int i = blockIdx.x * blockDim.x + threadIdx.x;
    if (i >= n4) return;
    float4 v = reinterpret_cast<const float4*>(s)[i];
    reinterpret_cast<__half2*>(o)[2 * i]     = __floats2half2_rn(v.x, v.y);
    reinterpret_cast<__half2*>(o)[2 * i + 1] = __floats2half2_rn(v.z, v.w);
}

__global__ void router_kernel(const float* __restrict__ x,
                              const float* __restrict__ wr) {
    int warp = (blockIdx.x * blockDim.x + threadIdx.x) >> 5;
    int lane = threadIdx.x & 31;
    if (warp >= N_TOK) return;
    const float* xr = x + (size_t)warp * D_MODEL;

    float logits[N_EXP];
#pragma unroll
    for (int e = 0; e < N_EXP; e++) {
        const float* w = wr + e * D_MODEL;
        float p = 0.f;
        for (int d = lane; d < D_MODEL; d += 32) p = fmaf(xr[d], w[d], p);
#pragma unroll
        for (int s = 16; s > 0; s >>= 1) p += __shfl_xor_sync(0xffffffffu, p, s);
        logits[e] = p;
    }
    if (lane == 0) {
        float mx = -3.4e38f;
#pragma unroll
        for (int e = 0; e < N_EXP; e++) {
            float v = fminf(fmaxf(logits[e], -1e4f), 1e4f);
            logits[e] = v; mx = fmaxf(mx, v);
        }
        float ex[N_EXP], s = 0.f;
#pragma unroll
        for (int e = 0; e < N_EXP; e++) { ex[e] = expf(logits[e] - mx); s += ex[e]; }
        float denom = s + 1e-8f;
        float probs[N_EXP];
#pragma unroll
        for (int e = 0; e < N_EXP; e++)
            probs[e] = fminf(fmaxf(ex[e] / denom, 1e-8f), 1.0f);
        int i0 = 0;
#pragma unroll
        for (int e = 1; e < N_EXP; e++) if (probs[e] > probs[i0]) i0 = e;
        int i1 = (i0 == 0) ? 1 : 0;
#pragma unroll
        for (int e = 0; e < N_EXP; e++)
            if (e != i0 && probs[e] > probs[i1]) i1 = e;
        float p0 = probs[i0], p1 = probs[i1];
        float rs = 1.f / (p0 + p1 + 1e-8f);
        d_tok_exp[2 * warp] = i0;  d_tok_exp[2 * warp + 1] = i1;
        d_tok_w[2 * warp] = p0 * rs; d_tok_w[2 * warp + 1] = p1 * rs;
        atomicAdd(&d_count[i0], 1); atomicAdd(&d_count[i1], 1);
    }
}

__global__ void offsets_kernel() {
    if (threadIdx.x == 0) {
        int o = 0;
        for (int e = 0; e < N_EXP; e++) {
            d_off[e] = o;
            o += ((d_count[e] + TILE - 1) / TILE) * TILE;
            d_cursor[e] = 0;
        }
        d_off[N_EXP] = o;
    }
}

__global__ void scatter_kernel() {
    int t = blockIdx.x * blockDim.x + threadIdx.x;
    if (t >= N_TOK) return;
#pragma unroll
    for (int k = 0; k < 2; k++) {
        int e = d_tok_exp[2 * t + k];
        int pos = d_off[e] + atomicAdd(&d_cursor[e], 1);
        d_row_token[pos]  = t;
        d_row_weight[pos] = d_tok_w[2 * t + k];
    }
}

// ===================== GEMM1: x(gather) @ wgu^T + fused SwiGLU -> d_H ========
// grid: (D_FF/64, ROWS/128). B rows interleaved: even = gate(f), odd = up(f).
// Pure fp16 HMMA, fp32 accumulate.
__global__ __launch_bounds__(256, 1)
void gemm1_mma(void) {
    extern __shared__ __align__(16) char dyn[];
    __shared__ int stok[128];

    const int tid  = threadIdx.x;
    const int wid  = tid >> 5;
    const int lane = tid & 31;
    const int rowStart  = blockIdx.y * 128;
    const int colStartF = blockIdx.x * 64;

    if (rowStart >= d_off[N_EXP]) return;
    int e = 0;
#pragma unroll
    for (int i = N_EXP - 1; i >= 0; i--) if (rowStart >= d_off[i]) { e = i; break; }

    if (tid < 128) stok[tid] = d_row_token[rowStart + tid];
    __syncthreads();

    const size_t wb = (size_t)e * 2 * D_FF * D_MODEL;
    const int wm = (wid & 1) * 64;
    const int wn = (wid >> 1) * 32;
    const uint32_t base = smem_u32(dyn);

    const int r0_ = tid >> 2, r1_ = r0_ + 64;
    const int u_  = tid & 3;
    const int rr0 = colStartF + (r0_ >> 1) + (r0_ & 1) * D_FF;
    const int rr1 = colStartF + (r1_ >> 1) + (r1_ & 1) * D_FF;

    float acc[4][4][4];
#pragma unroll
    for (int a = 0; a < 4; a++)
#pragma unroll
        for (int b = 0; b < 4; b++)
#pragma unroll
            for (int c = 0; c < 4; c++) acc[a][b][c] = 0.f;

#define G1_LOAD(stage, kt) do {                                                   \
    const uint32_t sb = base + (stage) * STAGE_BYTES;                             \
    const int k0 = (kt) * 32;                                                     \
    _Pragma("unroll")                                                             \
    for (int i = 0; i < 2; i++) {                                                 \
        int r  = i ? r1_ : r0_;                                                   \
        int rr = i ? rr1 : rr0;                                                   \
        uint32_t so = (uint32_t)((r * LDA + u_ * 8) * 2);                         \
        int t = stok[r];                                                          \
        uint32_t sz = (t >= 0) ? 16u : 0u;                                        \
        size_t ga = (size_t)(t >= 0 ? t : 0) * D_MODEL + k0 + u_ * 8;             \
        cp16(sb + A_OFF + so, d_x16 + ga, sz);                                    \
        size_t gb = wb + (size_t)rr * D_MODEL + k0 + u_ * 8;                      \
        cp16(sb + B_OFF + so, d_wgu16 + gb, 16u);                                 \
    }                                                                             \
} while (0)

    G1_LOAD(0, 0);
    CP_COMMIT();
    G1_LOAD(1, 1);
    CP_COMMIT();

    const int NKT = D_MODEL / 32;
#pragma unroll 1
    for (int kt = 0; kt < NKT; kt++) {
        CP_WAIT1();
        __syncthreads();
        if (kt + 2 < NKT) G1_LOAD((kt + 2) % NSTAGE, kt + 2);
        CP_COMMIT();

        const uint32_t sb = base + (kt % NSTAGE) * STAGE_BYTES;
        const uint32_t aA = sb + A_OFF, aB = sb + B_OFF;
#pragma unroll
        for (int ks = 0; ks < 2; ks++) {
            const int kk = ks * 16;
            uint32_t fA[4][4], fB[2][4];
#pragma unroll
            for (int mt = 0; mt < 4; mt++) {
                uint32_t off = (uint32_t)(((wm + mt * 16 + (lane & 15)) * LDA
                                           + kk + (lane >> 4) * 8) * 2);
                ldsm_x4(fA[mt][0], fA[mt][1], fA[mt][2], fA[mt][3], aA + off);
            }
#pragma unroll
            for (int p = 0; p < 2; p++) {
                int n0 = wn + p * 16;
                uint32_t off = (uint32_t)(((n0 + (lane & 7) + (lane >> 4) * 8) * LDA
                                           + kk + ((lane >> 3) & 1) * 8) * 2);
                ldsm_x4(fB[p][0], fB[p][1], fB[p][2], fB[p][3], aB + off);
            }
#pragma unroll
            for (int mt = 0; mt < 4; mt++)
#pragma unroll
                for (int nb = 0; nb < 4; nb++) {
                    int p = nb >> 1, h = (nb & 1) * 2;
                    mma16816(acc[mt][nb], fA[mt], fB[p][h], fB[p][h + 1]);
                }
        }
    }
#undef G1_LOAD

    // fused SwiGLU epilogue: column pair = (gate, up) of f = colStartF + col/2
    const int g  = lane >> 2;
    const int c2 = (lane & 3) * 2;
#pragma unroll
    for (int mt = 0; mt < 4; mt++) {
        int row0 = rowStart + wm + mt * 16 + g;
#pragma unroll
        for (int nb = 0; nb < 4; nb++) {
            int fcol = colStartF + ((wn + nb * 8 + c2) >> 1);
            float g0 = acc[mt][nb][0], u0 = acc[mt][nb][1];
            float g1 = acc[mt][nb][2], u1 = acc[mt][nb][3];
            float h0 = g0 * u0 / (1.f + expf(-u0));
            float h1 = g1 * u1 / (1.f + expf(-u1));
            d_H[(size_t)row0 * D_FF + fcol]       = __float2half_rn(h0);
            d_H[(size_t)(row0 + 8) * D_FF + fcol] = __float2half_rn(h1);
        }
    }
}

// ===================== GEMM2: H @ wd^T -> weighted scatter ===================
// grid: (1024/128, ROWS/128). K = 2048. Pure fp16 HMMA.
__global__ __launch_bounds__(256, 1)
void gemm2_mma(float* __restrict__ out) {
    extern __shared__ __align__(16) char dyn[];
    __shared__ int   stok[128];
    __shared__ float swt[128];

    const int tid  = threadIdx.x;
    const int wid  = tid >> 5;
    const int lane = tid & 31;
    const int rowStart = blockIdx.y * 128;
    const int colStart = blockIdx.x * 128;

    if (rowStart >= d_off[N_EXP]) return;
    int e = 0;
#pragma unroll
    for (int i = N_EXP - 1; i >= 0; i--) if (rowStart >= d_off[i]) { e = i; break; }

    if (tid < 128) {
        stok[tid] = d_row_token[rowStart + tid];
        swt[tid]  = d_row_weight[rowStart + tid];
    }
    __syncthreads();

    const size_t wb = (size_t)e * D_MODEL * D_FF;
    const int wm = (wid & 1) * 64;
    const int wn = (wid >> 1) * 32;
    const uint32_t base = smem_u32(dyn);

    const int r0_ = tid >> 2, r1_ = r0_ + 64;
    const int u_  = tid & 3;

    float acc[4][4][4];
#pragma unroll
    for (int a = 0; a < 4; a++)
#pragma unroll
        for (int b = 0; b < 4; b++)
#pragma unroll
            for (int c = 0; c < 4; c++) acc[a][b][c] = 0.f;

#define G2_LOAD(stage, kt) do {                                                   \
    const uint32_t sb = base + (stage) * STAGE_BYTES;                             \
    const int k0 = (kt) * 32;                                                     \
    _Pragma("unroll")                                                             \
    for (int i = 0; i < 2; i++) {                                                 \
        int r = i ? r1_ : r0_;                                                    \
        uint32_t so = (uint32_t)((r * LDA + u_ * 8) * 2);                         \
        size_t ga = (size_t)(rowStart + r) * D_FF + k0 + u_ * 8;                  \
        cp16(sb + A_OFF + so, d_H + ga, 16u);                                     \
        size_t gb = wb + (size_t)(colStart + r) * D_FF + k0 + u_ * 8;             \
        cp16(sb + B_OFF + so, d_wd16 + gb, 16u);                                  \
    }                                                                             \
} while (0)

    G2_LOAD(0, 0);
    CP_COMMIT();
    G2_LOAD(1, 1);
    CP_COMMIT();

    const int NKT = D_FF / 32;
#pragma unroll 1
    for (int kt = 0; kt < NKT; kt++) {
        CP_WAIT1();
        __syncthreads();
        if (kt + 2 < NKT) G2_LOAD((kt + 2) % NSTAGE, kt + 2);
        CP_COMMIT();

        const uint32_t sb = base + (kt % NSTAGE) * STAGE_BYTES;
        const uint32_t aA = sb + A_OFF, aB = sb + B_OFF;
#pragma unroll
        for (int ks = 0; ks < 2; ks++) {
            const int kk = ks * 16;
            uint32_t fA[4][4], fB[2][4];
#pragma unroll
            for (int mt = 0; mt < 4; mt++) {
                uint32_t off = (uint32_t)(((wm + mt * 16 + (lane & 15)) * LDA
                                           + kk + (lane >> 4) * 8) * 2);
                ldsm_x4(fA[mt][0], fA[mt][1], fA[mt][2], fA[mt][3], aA + off);
            }
#pragma unroll
            for (int p = 0; p < 2; p++) {
                int n0 = wn + p * 16;
                uint32_t off = (uint32_t)(((n0 + (lane & 7) + (lane >> 4) * 8) * LDA
                                           + kk + ((lane >> 3) & 1) * 8) * 2);
                ldsm_x4(fB[p][0], fB[p][1], fB[p][2], fB[p][3], aB + off);
            }
#pragma unroll
            for (int mt = 0; mt < 4; mt++)
#pragma unroll
                for (int nb = 0; nb < 4; nb++) {
                    int p = nb >> 1, h = (nb & 1) * 2;
                    mma16816(acc[mt][nb], fA[mt], fB[p][h], fB[p][h + 1]);
                }
        }
    }
#undef G2_LOAD

    // epilogue: weighted scatter-add (each out element gets exactly 2 fp32 adds)
    const int g  = lane >> 2;
    const int c2 = (lane & 3) * 2;
#pragma unroll
    for (int mt = 0; mt < 4; mt++) {
        int r0 = wm + mt * 16 + g;
        int t0 = stok[r0],     t1 = stok[r0 + 8];
        float w0 = swt[r0],    w1 = swt[r0 + 8];
#pragma unroll
        for (int nb = 0; nb < 4; nb++) {
            int col = colStart + wn + nb * 8 + c2;
            if (t0 >= 0) {
                float* o = out + (size_t)t0 * D_MODEL + col;
                atomicAdd(o,     w0 * acc[mt][nb][0]);
                atomicAdd(o + 1, w0 * acc[mt][nb][1]);
            }
            if (t1 >= 0) {
                float* o = out + (size_t)t1 * D_MODEL + col;
                atomicAdd(o,     w1 * acc[mt][nb][2]);
                atomicAdd(o + 1, w1 * acc[mt][nb][3]);
            }
        }
    }
}

// ===================== launch ================================================
extern "C" void kernel_launch(void* const* d_in, const int* in_sizes, int n_in,
                              void* d_out, int out_size) {
    const float* x   = (const float*)d_in[0];
    const float* wr  = (const float*)d_in[1];
    const float* wgu = (const float*)d_in[2];
    const float* wd  = (const float*)d_in[3];
    float* out = (float*)d_out;

    cudaFuncSetAttribute(gemm1_mma, cudaFuncAttributeMaxDynamicSharedMemorySize, DSMEM_BYTES);
    cudaFuncSetAttribute(gemm2_mma, cudaFuncAttributeMaxDynamicSharedMemorySize, DSMEM_BYTES);

    init_kernel<<<2048, 512>>>(out);

    __half *x16, *wgu16, *wd16;
    cudaGetSymbolAddress((void**)&x16,   d_x16);
    cudaGetSymbolAddress((void**)&wgu16, d_wgu16);
    cudaGetSymbolAddress((void**)&wd16,  d_wd16);

    { int n4 = N_TOK * D_MODEL / 4;
      cvt16_kernel<<<(n4 + 255) / 256, 256>>>(x, x16, n4); }
    { int n4 = N_EXP * 2 * D_FF * D_MODEL / 4;
      cvt16_kernel<<<(n4 + 255) / 256, 256>>>(wgu, wgu16, n4); }
    { int n4 = N_EXP * D_MODEL * D_FF / 4;
      cvt16_kernel<<<(n4 + 255) / 256, 256>>>(wd, wd16, n4); }

    router_kernel<<<N_TOK / 8, 256>>>(x, wr);
    offsets_kernel<<<1, 32>>>();
    scatter_kernel<<<(N_TOK + 255) / 256, 256>>>();

    gemm1_mma<<<dim3(D_FF / 64, ROWS / 128), 256, DSMEM_BYTES>>>();
    gemm2_mma<<<dim3(D_MODEL / 128, ROWS / 128), 256, DSMEM_BYTES>>>(out);
}

// round 15
// speedup vs baseline: 2.5765x; 1.8902x over previous
#include <cuda_runtime.h>
#include <cuda_fp16.h>
#include <math.h>
#include <stdint.h>

#define N_TOK   4096
#define D_MODEL 1024
#define D_FF    2048
#define N_EXP   8
#define ROWS    9216
#define TILE    128
#define LDA     40          /* padded SMEM row stride in halves (80B, conflict-free ldmatrix) */

#define BUF_BYTES   (128 * LDA * 2)          /* 10240 B per tile buffer */
#define A_OFF       0
#define B_OFF       (1 * BUF_BYTES)
#define STAGE_BYTES (2 * BUF_BYTES)          /* 20480 B */
#define NSTAGE      3
#define DSMEM_BYTES (NSTAGE * STAGE_BYTES)   /* 61440 B; x2 blocks = 122880 <= 227KB */

// ===================== helpers ==============================================
__device__ __forceinline__ uint32_t smem_u32(const void* p) {
    uint32_t a;
    asm("{ .reg .u64 t; cvta.to.shared.u64 t, %1; cvt.u32.u64 %0, t; }" : "=r"(a) : "l"(p));
    return a;
}
__device__ __forceinline__ void ldsm_x4(uint32_t& r0, uint32_t& r1, uint32_t& r2, uint32_t& r3,
                                        uint32_t addr) {
    asm volatile("ldmatrix.sync.aligned.m8n8.x4.shared.b16 {%0,%1,%2,%3}, [%4];"
                 : "=r"(r0), "=r"(r1), "=r"(r2), "=r"(r3) : "r"(addr));
}
__device__ __forceinline__ void mma16816(float* c, const uint32_t* a, uint32_t b0, uint32_t b1) {
    asm volatile(
        "mma.sync.aligned.m16n8k16.row.col.f32.f16.f16.f32 "
        "{%0,%1,%2,%3}, {%4,%5,%6,%7}, {%8,%9}, {%0,%1,%2,%3};"
        : "+f"(c[0]), "+f"(c[1]), "+f"(c[2]), "+f"(c[3])
        : "r"(a[0]), "r"(a[1]), "r"(a[2]), "r"(a[3]), "r"(b0), "r"(b1));
}
__device__ __forceinline__ void cp16(uint32_t saddr, const void* g, uint32_t src_sz) {
    asm volatile("cp.async.cg.shared.global [%0], [%1], 16, %2;"
                 :: "r"(saddr), "l"(g), "r"(src_sz));
}
#define CP_COMMIT() asm volatile("cp.async.commit_group;" ::: "memory")
#define CP_WAIT1()  asm volatile("cp.async.wait_group 1;" ::: "memory")

// ===================== scratch ==============================================
__device__ int   d_tok_exp[N_TOK * 2];
__device__ float d_tok_w[N_TOK * 2];
__device__ int   d_count[N_EXP];
__device__ int   d_off[N_EXP + 1];
__device__ int   d_cursor[N_EXP];
__device__ int   d_row_token[ROWS];
__device__ float d_row_weight[ROWS];

__device__ __half d_x16[(size_t)N_TOK * D_MODEL];
__device__ __half d_wgu16[(size_t)N_EXP * 2 * D_FF * D_MODEL];
__device__ __half d_wd16[(size_t)N_EXP * D_MODEL * D_FF];
__device__ __half d_H[(size_t)ROWS * D_FF];

// ===================== small kernels ========================================
__global__ void init_kernel(float* __restrict__ out) {
    int i = blockIdx.x * blockDim.x + threadIdx.x;
    int stride = gridDim.x * blockDim.x;
    for (int j = i; j < N_TOK * D_MODEL; j += stride) out[j] = 0.f;
    if (i < ROWS) { d_row_token[i] = -1; d_row_weight[i] = 0.f; }
    if (i < N_EXP) d_count[i] = 0;
}

// fp32 -> fp16
__global__ void cvt16_kernel(const float* __restrict__ s, __half* __restrict__ o, int n4) {
    int i = blockIdx.x * blockDim.x + threadIdx.x;
    if (i >= n4) return;
    float4 v = reinterpret_cast<const float4*>(s)[i];
    reinterpret_cast<__half2*>(o)[2 * i]     = __floats2half2_rn(v.x, v.y);
    reinterpret_cast<__half2*>(o)[2 * i + 1] = __floats2half2_rn(v.z, v.w);
}

__global__ void router_kernel(const float* __restrict__ x,
                              const float* __restrict__ wr) {
    int warp = (blockIdx.x * blockDim.x + threadIdx.x) >> 5;
    int lane = threadIdx.x & 31;
    if (warp >= N_TOK) return;
    const float* xr = x + (size_t)warp * D_MODEL;

    float logits[N_EXP];
#pragma unroll
    for (int e = 0; e < N_EXP; e++) {
        const float* w = wr + e * D_MODEL;
        float p = 0.f;
        for (int d = lane; d < D_MODEL; d += 32) p = fmaf(xr[d], w[d], p);
#pragma unroll
        for (int s = 16; s > 0; s >>= 1) p += __shfl_xor_sync(0xffffffffu, p, s);
        logits[e] = p;
    }
    if (lane == 0) {
        float mx = -3.4e38f;
#pragma unroll
        for (int e = 0; e < N_EXP; e++) {
            float v = fminf(fmaxf(logits[e], -1e4f), 1e4f);
            logits[e] = v; mx = fmaxf(mx, v);
        }
        float ex[N_EXP], s = 0.f;
#pragma unroll
        for (int e = 0; e < N_EXP; e++) { ex[e] = expf(logits[e] - mx); s += ex[e]; }
        float denom = s + 1e-8f;
        float probs[N_EXP];
#pragma unroll
        for (int e = 0; e < N_EXP; e++)
            probs[e] = fminf(fmaxf(ex[e] / denom, 1e-8f), 1.0f);
        int i0 = 0;
#pragma unroll
        for (int e = 1; e < N_EXP; e++) if (probs[e] > probs[i0]) i0 = e;
        int i1 = (i0 == 0) ? 1 : 0;
#pragma unroll
        for (int e = 0; e < N_EXP; e++)
            if (e != i0 && probs[e] > probs[i1]) i1 = e;
        float p0 = probs[i0], p1 = probs[i1];
        float rs = 1.f / (p0 + p1 + 1e-8f);
        d_tok_exp[2 * warp] = i0;  d_tok_exp[2 * warp + 1] = i1;
        d_tok_w[2 * warp] = p0 * rs; d_tok_w[2 * warp + 1] = p1 * rs;
        atomicAdd(&d_count[i0], 1); atomicAdd(&d_count[i1], 1);
    }
}

__global__ void offsets_kernel() {
    if (threadIdx.x == 0) {
        int o = 0;
        for (int e = 0; e < N_EXP; e++) {
            d_off[e] = o;
            o += ((d_count[e] + TILE - 1) / TILE) * TILE;
            d_cursor[e] = 0;
        }
        d_off[N_EXP] = o;
    }
}

__global__ void scatter_kernel() {
    int t = blockIdx.x * blockDim.x + threadIdx.x;
    if (t >= N_TOK) return;
#pragma unroll
    for (int k = 0; k < 2; k++) {
        int e = d_tok_exp[2 * t + k];
        int pos = d_off[e] + atomicAdd(&d_cursor[e], 1);
        d_row_token[pos]  = t;
        d_row_weight[pos] = d_tok_w[2 * t + k];
    }
}

// ===================== GEMM1: x(gather) @ wgu^T + fused SwiGLU -> d_H ========
// grid: (D_FF/64, ROWS/128). B rows interleaved: even = gate(f), odd = up(f).
// Pure fp16 HMMA, fp32 accumulate. 2 blocks/SM for latency hiding.
__global__ __launch_bounds__(256, 2)
void gemm1_mma(void) {
    extern __shared__ __align__(16) char dyn[];
    __shared__ int stok[128];

    const int tid  = threadIdx.x;
    const int wid  = tid >> 5;
    const int lane = tid & 31;
    const int rowStart  = blockIdx.y * 128;
    const int colStartF = blockIdx.x * 64;

    if (rowStart >= d_off[N_EXP]) return;
    int e = 0;
#pragma unroll
    for (int i = N_EXP - 1; i >= 0; i--) if (rowStart >= d_off[i]) { e = i; break; }

    if (tid < 128) stok[tid] = d_row_token[rowStart + tid];
    __syncthreads();

    const size_t wb = (size_t)e * 2 * D_FF * D_MODEL;
    const int wm = (wid & 1) * 64;
    const int wn = (wid >> 1) * 32;
    const uint32_t base = smem_u32(dyn);

    const int r0_ = tid >> 2, r1_ = r0_ + 64;
    const int u_  = tid & 3;
    const int rr0 = colStartF + (r0_ >> 1) + (r0_ & 1) * D_FF;
    const int rr1 = colStartF + (r1_ >> 1) + (r1_ & 1) * D_FF;

    float acc[4][4][4];
#pragma unroll
    for (int a = 0; a < 4; a++)
#pragma unroll
        for (int b = 0; b < 4; b++)
#pragma unroll
            for (int c = 0; c < 4; c++) acc[a][b][c] = 0.f;

#define G1_LOAD(stage, kt) do {                                                   \
    const uint32_t sb = base + (stage) * STAGE_BYTES;                             \
    const int k0 = (kt) * 32;                                                     \
    _Pragma("unroll")                                                             \
    for (int i = 0; i < 2; i++) {                                                 \
        int r  = i ? r1_ : r0_;                                                   \
        int rr = i ? rr1 : rr0;                                                   \
        uint32_t so = (uint32_t)((r * LDA + u_ * 8) * 2);                         \
        int t = stok[r];                                                          \
        uint32_t sz = (t >= 0) ? 16u : 0u;                                        \
        size_t ga = (size_t)(t >= 0 ? t : 0) * D_MODEL + k0 + u_ * 8;             \
        cp16(sb + A_OFF + so, d_x16 + ga, sz);                                    \
        size_t gb = wb + (size_t)rr * D_MODEL + k0 + u_ * 8;                      \
        cp16(sb + B_OFF + so, d_wgu16 + gb, 16u);                                 \
    }                                                                             \
} while (0)

    G1_LOAD(0, 0);
    CP_COMMIT();
    G1_LOAD(1, 1);
    CP_COMMIT();

    const int NKT = D_MODEL / 32;
#pragma unroll 1
    for (int kt = 0; kt < NKT; kt++) {
        CP_WAIT1();
        __syncthreads();
        if (kt + 2 < NKT) G1_LOAD((kt + 2) % NSTAGE, kt + 2);
        CP_COMMIT();

        const uint32_t sb = base + (kt % NSTAGE) * STAGE_BYTES;
        const uint32_t aA = sb + A_OFF, aB = sb + B_OFF;
#pragma unroll
        for (int ks = 0; ks < 2; ks++) {
            const int kk = ks * 16;
            uint32_t fA[4][4], fB[2][4];
#pragma unroll
            for (int mt = 0; mt < 4; mt++) {
                uint32_t off = (uint32_t)(((wm + mt * 16 + (lane & 15)) * LDA
                                           + kk + (lane >> 4) * 8) * 2);
                ldsm_x4(fA[mt][0], fA[mt][1], fA[mt][2], fA[mt][3], aA + off);
            }
#pragma unroll
            for (int p = 0; p < 2; p++) {
                int n0 = wn + p * 16;
                uint32_t off = (uint32_t)(((n0 + (lane & 7) + (lane >> 4) * 8) * LDA
                                           + kk + ((lane >> 3) & 1) * 8) * 2);
                ldsm_x4(fB[p][0], fB[p][1], fB[p][2], fB[p][3], aB + off);
            }
#pragma unroll
            for (int mt = 0; mt < 4; mt++)
#pragma unroll
                for (int nb = 0; nb < 4; nb++) {
                    int p = nb >> 1, h = (nb & 1) * 2;
                    mma16816(acc[mt][nb], fA[mt], fB[p][h], fB[p][h + 1]);
                }
        }
    }
#undef G1_LOAD

    // fused SwiGLU epilogue: column pair = (gate, up) of f = colStartF + col/2
    const int g  = lane >> 2;
    const int c2 = (lane & 3) * 2;
#pragma unroll
    for (int mt = 0; mt < 4; mt++) {
        int row0 = rowStart + wm + mt * 16 + g;
#pragma unroll
        for (int nb = 0; nb < 4; nb++) {
            int fcol = colStartF + ((wn + nb * 8 + c2) >> 1);
            float g0 = acc[mt][nb][0], u0 = acc[mt][nb][1];
            float g1 = acc[mt][nb][2], u1 = acc[mt][nb][3];
            float h0 = g0 * u0 / (1.f + expf(-u0));
            float h1 = g1 * u1 / (1.f + expf(-u1));
            d_H[(size_t)row0 * D_FF + fcol]       = __float2half_rn(h0);
            d_H[(size_t)(row0 + 8) * D_FF + fcol] = __float2half_rn(h1);
        }
    }
}

// ===================== GEMM2: H @ wd^T -> weighted scatter ===================
// grid: (1024/128, ROWS/128). K = 2048. Pure fp16 HMMA. 2 blocks/SM.
__global__ __launch_bounds__(256, 2)
void gemm2_mma(float* __restrict__ out) {
    extern __shared__ __align__(16) char dyn[];
    __shared__ int   stok[128];
    __shared__ float swt[128];

    const int tid  = threadIdx.x;
    const int wid  = tid >> 5;
    const int lane = tid & 31;
    const int rowStart = blockIdx.y * 128;
    const int colStart = blockIdx.x * 128;

    if (rowStart >= d_off[N_EXP]) return;
    int e = 0;
#pragma unroll
    for (int i = N_EXP - 1; i >= 0; i--) if (rowStart >= d_off[i]) { e = i; break; }

    if (tid < 128) {
        stok[tid] = d_row_token[rowStart + tid];
        swt[tid]  = d_row_weight[rowStart + tid];
    }
    __syncthreads();

    const size_t wb = (size_t)e * D_MODEL * D_FF;
    const int wm = (wid & 1) * 64;
    const int wn = (wid >> 1) * 32;
    const uint32_t base = smem_u32(dyn);

    const int r0_ = tid >> 2, r1_ = r0_ + 64;
    const int u_  = tid & 3;

    float acc[4][4][4];
#pragma unroll
    for (int a = 0; a < 4; a++)
#pragma unroll
        for (int b = 0; b < 4; b++)
#pragma unroll
            for (int c = 0; c < 4; c++) acc[a][b][c] = 0.f;

#define G2_LOAD(stage, kt) do {                                                   \
    const uint32_t sb = base + (stage) * STAGE_BYTES;                             \
    const int k0 = (kt) * 32;                                                     \
    _Pragma("unroll")                                                             \
    for (int i = 0; i < 2; i++) {                                                 \
        int r = i ? r1_ : r0_;                                                    \
        uint32_t so = (uint32_t)((r * LDA + u_ * 8) * 2);                         \
        size_t ga = (size_t)(rowStart + r) * D_FF + k0 + u_ * 8;                  \
        cp16(sb + A_OFF + so, d_H + ga, 16u);                                     \
        size_t gb = wb + (size_t)(colStart + r) * D_FF + k0 + u_ * 8;             \
        cp16(sb + B_OFF + so, d_wd16 + gb, 16u);                                  \
    }                                                                             \
} while (0)

    G2_LOAD(0, 0);
    CP_COMMIT();
    G2_LOAD(1, 1);
    CP_COMMIT();

    const int NKT = D_FF / 32;
#pragma unroll 1
    for (int kt = 0; kt < NKT; kt++) {
        CP_WAIT1();
        __syncthreads();
        if (kt + 2 < NKT) G2_LOAD((kt + 2) % NSTAGE, kt + 2);
        CP_COMMIT();

        const uint32_t sb = base + (kt % NSTAGE) * STAGE_BYTES;
        const uint32_t aA = sb + A_OFF, aB = sb + B_OFF;
#pragma unroll
        for (int ks = 0; ks < 2; ks++) {
            const int kk = ks * 16;
            uint32_t fA[4][4], fB[2][4];
#pragma unroll
            for (int mt = 0; mt < 4; mt++) {
                uint32_t off = (uint32_t)(((wm + mt * 16 + (lane & 15)) * LDA
                                           + kk + (lane >> 4) * 8) * 2);
                ldsm_x4(fA[mt][0], fA[mt][1], fA[mt][2], fA[mt][3], aA + off);
            }
#pragma unroll
            for (int p = 0; p < 2; p++) {
                int n0 = wn + p * 16;
                uint32_t off = (uint32_t)(((n0 + (lane & 7) + (lane >> 4) * 8) * LDA
                                           + kk + ((lane >> 3) & 1) * 8) * 2);
                ldsm_x4(fB[p][0], fB[p][1], fB[p][2], fB[p][3], aB + off);
            }
#pragma unroll
            for (int mt = 0; mt < 4; mt++)
#pragma unroll
                for (int nb = 0; nb < 4; nb++) {
                    int p = nb >> 1, h = (nb & 1) * 2;
                    mma16816(acc[mt][nb], fA[mt], fB[p][h], fB[p][h + 1]);
                }
        }
    }
#undef G2_LOAD

    // epilogue: weighted scatter-add (each out element gets exactly 2 fp32 adds)
    const int g  = lane >> 2;
    const int c2 = (lane & 3) * 2;
#pragma unroll
    for (int mt = 0; mt < 4; mt++) {
        int r0 = wm + mt * 16 + g;
        int t0 = stok[r0],     t1 = stok[r0 + 8];
        float w0 = swt[r0],    w1 = swt[r0 + 8];
#pragma unroll
        for (int nb = 0; nb < 4; nb++) {
            int col = colStart + wn + nb * 8 + c2;
            if (t0 >= 0) {
                float* o = out + (size_t)t0 * D_MODEL + col;
                atomicAdd(o,     w0 * acc[mt][nb][0]);
                atomicAdd(o + 1, w0 * acc[mt][nb][1]);
            }
            if (t1 >= 0) {
                float* o = out + (size_t)t1 * D_MODEL + col;
                atomicAdd(o,     w1 * acc[mt][nb][2]);
                atomicAdd(o + 1, w1 * acc[mt][nb][3]);
            }
        }
    }
}

// ===================== launch ================================================
extern "C" void kernel_launch(void* const* d_in, const int* in_sizes, int n_in,
                              void* d_out, int out_size) {
    const float* x   = (const float*)d_in[0];
    const float* wr  = (const float*)d_in[1];
    const float* wgu = (const float*)d_in[2];
    const float* wd  = (const float*)d_in[3];
    float* out = (float*)d_out;

    cudaFuncSetAttribute(gemm1_mma, cudaFuncAttributeMaxDynamicSharedMemorySize, DSMEM_BYTES);
    cudaFuncSetAttribute(gemm2_mma, cudaFuncAttributeMaxDynamicSharedMemorySize, DSMEM_BYTES);

    init_kernel<<<2048, 512>>>(out);

    __half *x16, *wgu16, *wd16;
    cudaGetSymbolAddress((void**)&x16,   d_x16);
    cudaGetSymbolAddress((void**)&wgu16, d_wgu16);
    cudaGetSymbolAddress((void**)&wd16,  d_wd16);

    { int n4 = N_TOK * D_MODEL / 4;
      cvt16_kernel<<<(n4 + 255) / 256, 256>>>(x, x16, n4); }
    { int n4 = N_EXP * 2 * D_FF * D_MODEL / 4;
      cvt16_kernel<<<(n4 + 255) / 256, 256>>>(wgu, wgu16, n4); }
    { int n4 = N_EXP * D_MODEL * D_FF / 4;
      cvt16_kernel<<<(n4 + 255) / 256, 256>>>(wd, wd16, n4); }

    router_kernel<<<N_TOK / 8, 256>>>(x, wr);
    offsets_kernel<<<1, 32>>>();
    scatter_kernel<<<(N_TOK + 255) / 256, 256>>>();

    gemm1_mma<<<dim3(D_FF / 64, ROWS / 128), 256, DSMEM_BYTES>>>();
    gemm2_mma<<<dim3(D_MODEL / 128, ROWS / 128), 256, DSMEM_BYTES>>>(out);
}